// round 1
// baseline (speedup 1.0000x reference)
#include <cuda_runtime.h>
#include <math.h>

// ---------------------------------------------------------------------------
// TCVAE loss, exploiting the algebraic telescoping of the KL decomposition:
//   kl_loss = ALPHA*MI + BETA*TC + GAMMA*DWKL   with ALPHA=BETA=GAMMA=1
//           = mean_i( log q(z|x)_i ) - mean_i( log p(z)_i )
// so the O(B^2*D) pairwise logsumexp terms cancel exactly.
//
// Remaining work:
//   recon_loss = sum |x - recon| / (B*T)
//   kl_loss    = (1/B) * sum_{i,d} [ -0.5*((z-mu)^2*e^{-lv} + lv)
//                                    +0.5*( z^2*e^{-1}      + 1 ) ]
// (log(2*pi) terms cancel elementwise.)
// ---------------------------------------------------------------------------

__device__ double g_recon_sum;
__device__ double g_kl_sum;

__global__ void tcvae_zero_kernel() {
    g_recon_sum = 0.0;
    g_kl_sum = 0.0;
}

__global__ void __launch_bounds__(256) tcvae_reduce_kernel(
    const float4* __restrict__ recon4,
    const float4* __restrict__ x4,
    int n_bt4,                       // (B*T)/4
    const float* __restrict__ mu,
    const float* __restrict__ log_var,
    const float* __restrict__ z,
    int n_bd)                        // B*D
{
    const float INV_E = 0.36787944117144233f;  // e^{-1}

    float racc = 0.0f;
    float kacc = 0.0f;

    int tid = blockIdx.x * blockDim.x + threadIdx.x;
    int stride = gridDim.x * blockDim.x;

    // reconstruction L1 term (vectorized)
    for (int i = tid; i < n_bt4; i += stride) {
        float4 a = recon4[i];
        float4 b = x4[i];
        racc += fabsf(b.x - a.x) + fabsf(b.y - a.y)
              + fabsf(b.z - a.z) + fabsf(b.w - a.w);
    }

    // KL term: gauss(z; mu, lv) - gauss(z; 0, 1)   (log2pi cancels)
    for (int i = tid; i < n_bd; i += stride) {
        float m  = mu[i];
        float lv = log_var[i];
        float zz = z[i];
        float t  = zz - m;
        float g_post  = -0.5f * (t * t * expf(-lv) + lv);
        float g_prior = -0.5f * (zz * zz * INV_E + 1.0f);
        kacc += g_post - g_prior;
    }

    // warp reduction
    #pragma unroll
    for (int o = 16; o > 0; o >>= 1) {
        racc += __shfl_xor_sync(0xFFFFFFFFu, racc, o);
        kacc += __shfl_xor_sync(0xFFFFFFFFu, kacc, o);
    }

    __shared__ float sr[8];
    __shared__ float sk[8];
    int lane = threadIdx.x & 31;
    int warp = threadIdx.x >> 5;
    if (lane == 0) { sr[warp] = racc; sk[warp] = kacc; }
    __syncthreads();

    if (warp == 0) {
        int nwarps = blockDim.x >> 5;
        racc = (lane < nwarps) ? sr[lane] : 0.0f;
        kacc = (lane < nwarps) ? sk[lane] : 0.0f;
        #pragma unroll
        for (int o = 4; o > 0; o >>= 1) {
            racc += __shfl_xor_sync(0xFFFFFFFFu, racc, o);
            kacc += __shfl_xor_sync(0xFFFFFFFFu, kacc, o);
        }
        if (lane == 0) {
            atomicAdd(&g_recon_sum, (double)racc);
            atomicAdd(&g_kl_sum, (double)kacc);
        }
    }
}

__global__ void tcvae_finalize_kernel(float* __restrict__ out,
                                      int n_bt, int batch) {
    float recon_loss = (float)(g_recon_sum / (double)n_bt);
    float kl_loss    = (float)(g_kl_sum / (double)batch);
    out[0] = recon_loss + kl_loss;  // total_loss
    out[1] = recon_loss;
    out[2] = kl_loss;
}

extern "C" void kernel_launch(void* const* d_in, const int* in_sizes, int n_in,
                              void* d_out, int out_size) {
    const float* recon   = (const float*)d_in[0];  // [B, T]
    const float* x       = (const float*)d_in[1];  // [B, T]
    const float* mu      = (const float*)d_in[2];  // [B, D]
    const float* log_var = (const float*)d_in[3];  // [B, D]
    const float* z       = (const float*)d_in[4];  // [B, D]
    // d_in[5] = dataset_size: unused after telescoping cancellation.

    int n_bt = in_sizes[0];          // B*T = 1048576
    int n_bd = in_sizes[2];          // B*D = 65536
    const int batch = 2048;          // B (fixed problem instance)

    float* out = (float*)d_out;

    tcvae_zero_kernel<<<1, 1>>>();

    int n_bt4 = n_bt / 4;
    int block = 256;
    int grid = 1024;                 // 262144 threads: 1 float4 each for recon
    tcvae_reduce_kernel<<<grid, block>>>(
        (const float4*)recon, (const float4*)x, n_bt4,
        mu, log_var, z, n_bd);

    tcvae_finalize_kernel<<<1, 1>>>(out, n_bt, batch);
}